// round 5
// baseline (speedup 1.0000x reference)
#include <cuda_runtime.h>
#include <cuda_bf16.h>
#include <math.h>

// Problem constants
#define BB 2
#define TT 2048
#define CC 2048
#define HH 16
#define DKK 128
#define DVV 128
#define KEY_DIM 2048
#define VALUE_DIM 2048
#define CONV_DIM 6144
#define QKVZ_N 8192
#define BT 4096   // B*T

// ---------------- scratch (static device globals; no allocation) -------------
__device__ float g_qkvz[(size_t)BT * QKVZ_N];   // 128 MiB: x @ W_qkvz
__device__ float g_y[(size_t)BT * CONV_DIM];    // 96 MiB
__device__ float g_beta[(size_t)BT * HH];
__device__ float g_alpha[(size_t)BT * HH];
__device__ float g_att[(size_t)BT * VALUE_DIM]; // 32 MiB
__device__ float g_go[(size_t)BT * VALUE_DIM];  // 32 MiB

// ---------------- tf32 tensor-core GEMM --------------------------------------
// C[M,N] = A[M,K] * B[K,N], row-major. CTA tile 128x256, BK=16, 256 threads,
// 8 warps as 2x4, warp tile 64x64. Double-buffered smem, XOR bank swizzle
// (col ^ ((k&3)<<3)) => conflict-free fragment reads, 48KB smem exactly.
__device__ __forceinline__ unsigned f2tf32(float x) {
    unsigned r;
    asm("cvt.rna.tf32.f32 %0, %1;" : "=r"(r) : "f"(x));
    return r;
}

__device__ __forceinline__ void mma_tf32(float* d, const unsigned* a,
                                         const unsigned* b) {
    asm volatile(
        "mma.sync.aligned.m16n8k8.row.col.f32.tf32.tf32.f32 "
        "{%0,%1,%2,%3}, {%4,%5,%6,%7}, {%8,%9}, {%0,%1,%2,%3};\n"
        : "+f"(d[0]), "+f"(d[1]), "+f"(d[2]), "+f"(d[3])
        : "r"(a[0]), "r"(a[1]), "r"(a[2]), "r"(a[3]),
          "r"(b[0]), "r"(b[1]));
}

__global__ void __launch_bounds__(256)
tf32gemm(const float* __restrict__ A, const float* __restrict__ Bm,
         float* __restrict__ Cm, int M, int N, int Kd)
{
    __shared__ unsigned As[2][16][128];   // [buf][k][m^swz]  16 KB
    __shared__ unsigned Bs[2][16][256];   // [buf][k][n^swz]  32 KB

    const int tid  = threadIdx.x;
    const int bm   = blockIdx.y * 128;
    const int bn   = blockIdx.x * 256;
    const int lane = tid & 31;
    const int warp = tid >> 5;
    const int wm   = (warp >> 2) * 64;    // 0 / 64
    const int wn   = (warp & 3) * 64;     // 0 / 64 / 128 / 192
    const int tig  = lane & 3;
    const int gid  = lane >> 2;
    const int fsw  = tig << 3;            // fragment-read swizzle

    // A loader: row ar (0..127), k-base ka (0 or 8); lane pairs cover 64B rows
    const int ar = tid >> 1;
    const int ka = (tid & 1) * 8;
    // B loader: k-row br (0..15), col base bc, 4 float4 chunks 64 apart
    const int br = tid >> 4;
    const int bc = (tid & 15) * 4;
    const int bsw = (br & 3) << 3;

    const float* Ap = A  + (size_t)(bm + ar) * Kd + ka;
    const float* Bp = Bm + (size_t)br * N + bn + bc;

    float acc[4][8][4];
    #pragma unroll
    for (int i = 0; i < 4; i++)
        #pragma unroll
        for (int j = 0; j < 8; j++)
            #pragma unroll
            for (int r = 0; r < 4; r++) acc[i][j][r] = 0.f;

    float4 av0, av1, bv0, bv1, bv2, bv3;
    av0 = *(const float4*)Ap;
    av1 = *(const float4*)(Ap + 4);
    bv0 = *(const float4*)(Bp);
    bv1 = *(const float4*)(Bp + 64);
    bv2 = *(const float4*)(Bp + 128);
    bv3 = *(const float4*)(Bp + 192);

    // store tile into buffer 0
    {
        float a8[8] = {av0.x, av0.y, av0.z, av0.w, av1.x, av1.y, av1.z, av1.w};
        #pragma unroll
        for (int j = 0; j < 8; j++)
            As[0][ka + j][ar ^ (((ka + j) & 3) << 3)] = f2tf32(a8[j]);
        uint4 u;
        u = make_uint4(f2tf32(bv0.x), f2tf32(bv0.y), f2tf32(bv0.z), f2tf32(bv0.w));
        *(uint4*)&Bs[0][br][(bc +   0) ^ bsw] = u;
        u = make_uint4(f2tf32(bv1.x), f2tf32(bv1.y), f2tf32(bv1.z), f2tf32(bv1.w));
        *(uint4*)&Bs[0][br][(bc +  64) ^ bsw] = u;
        u = make_uint4(f2tf32(bv2.x), f2tf32(bv2.y), f2tf32(bv2.z), f2tf32(bv2.w));
        *(uint4*)&Bs[0][br][(bc + 128) ^ bsw] = u;
        u = make_uint4(f2tf32(bv3.x), f2tf32(bv3.y), f2tf32(bv3.z), f2tf32(bv3.w));
        *(uint4*)&Bs[0][br][(bc + 192) ^ bsw] = u;
    }
    __syncthreads();

    int buf = 0;
    for (int k0 = 0; k0 < Kd; k0 += 16) {
        const bool more = (k0 + 16) < Kd;
        if (more) {
            Ap += 16;
            Bp += (size_t)16 * N;
            av0 = *(const float4*)Ap;
            av1 = *(const float4*)(Ap + 4);
            bv0 = *(const float4*)(Bp);
            bv1 = *(const float4*)(Bp + 64);
            bv2 = *(const float4*)(Bp + 128);
            bv3 = *(const float4*)(Bp + 192);
        }

        #pragma unroll
        for (int ks = 0; ks < 16; ks += 8) {
            const int kr0 = ks + tig;
            const int kr1 = ks + tig + 4;
            unsigned af[4][4], bf[8][2];
            #pragma unroll
            for (int mt = 0; mt < 4; mt++) {
                const int mb = wm + mt * 16;
                af[mt][0] = As[buf][kr0][(mb + gid)     ^ fsw];
                af[mt][1] = As[buf][kr0][(mb + gid + 8) ^ fsw];
                af[mt][2] = As[buf][kr1][(mb + gid)     ^ fsw];
                af[mt][3] = As[buf][kr1][(mb + gid + 8) ^ fsw];
            }
            #pragma unroll
            for (int nt = 0; nt < 8; nt++) {
                const int nb = wn + nt * 8;
                bf[nt][0] = Bs[buf][kr0][(nb + gid) ^ fsw];
                bf[nt][1] = Bs[buf][kr1][(nb + gid) ^ fsw];
            }
            #pragma unroll
            for (int mt = 0; mt < 4; mt++)
                #pragma unroll
                for (int nt = 0; nt < 8; nt++)
                    mma_tf32(acc[mt][nt], af[mt], bf[nt]);
        }

        if (more) {
            const int nb2 = buf ^ 1;
            float a8[8] = {av0.x, av0.y, av0.z, av0.w, av1.x, av1.y, av1.z, av1.w};
            #pragma unroll
            for (int j = 0; j < 8; j++)
                As[nb2][ka + j][ar ^ (((ka + j) & 3) << 3)] = f2tf32(a8[j]);
            uint4 u;
            u = make_uint4(f2tf32(bv0.x), f2tf32(bv0.y), f2tf32(bv0.z), f2tf32(bv0.w));
            *(uint4*)&Bs[nb2][br][(bc +   0) ^ bsw] = u;
            u = make_uint4(f2tf32(bv1.x), f2tf32(bv1.y), f2tf32(bv1.z), f2tf32(bv1.w));
            *(uint4*)&Bs[nb2][br][(bc +  64) ^ bsw] = u;
            u = make_uint4(f2tf32(bv2.x), f2tf32(bv2.y), f2tf32(bv2.z), f2tf32(bv2.w));
            *(uint4*)&Bs[nb2][br][(bc + 128) ^ bsw] = u;
            u = make_uint4(f2tf32(bv3.x), f2tf32(bv3.y), f2tf32(bv3.z), f2tf32(bv3.w));
            *(uint4*)&Bs[nb2][br][(bc + 192) ^ bsw] = u;
        }
        __syncthreads();
        buf ^= 1;
    }

    #pragma unroll
    for (int mt = 0; mt < 4; mt++) {
        const int row = bm + wm + mt * 16 + gid;
        #pragma unroll
        for (int nt = 0; nt < 8; nt++) {
            const int col = bn + wn + nt * 8 + 2 * tig;
            *(float2*)&Cm[(size_t)row * N + col]       = make_float2(acc[mt][nt][0], acc[mt][nt][1]);
            *(float2*)&Cm[(size_t)(row + 8) * N + col] = make_float2(acc[mt][nt][2], acc[mt][nt][3]);
        }
    }
}

// ---------------- beta/alpha: sigmoid(x @ W_b), sigmoid(x @ W_a) -------------
__global__ void __launch_bounds__(128)
ba_kernel(const float* __restrict__ x, const float* __restrict__ Wb,
          const float* __restrict__ Wa, float* __restrict__ beta,
          float* __restrict__ alpha)
{
    __shared__ float xs[CC];
    const int row = blockIdx.x;
    const float* xr = x + (size_t)row * CC;
    for (int i = threadIdx.x; i < CC; i += 128) xs[i] = xr[i];
    __syncthreads();

    const int g = threadIdx.x >> 2;
    const int l = threadIdx.x & 3;
    const float* W = (g < 16) ? Wb : Wa;
    const int h = g & 15;
    float s = 0.f;
    for (int cidx = l; cidx < CC; cidx += 4)
        s = fmaf(xs[cidx], W[cidx * HH + h], s);
    s += __shfl_down_sync(0xffffffffu, s, 2);
    s += __shfl_down_sync(0xffffffffu, s, 1);
    if (l == 0) {
        float v = 1.f / (1.f + expf(-s));
        if (g < 16) beta[(size_t)row * HH + h] = v;
        else        alpha[(size_t)row * HH + h] = v;
    }
}

// ---------------- causal depthwise conv(K=4) + silu + l2norm of q,k ----------
__global__ void __launch_bounds__(256)
conv_kernel(const float* __restrict__ qkvz, const float* __restrict__ conv_w,
            const float* __restrict__ conv_state, const int* __restrict__ input_pos,
            float* __restrict__ y_out)
{
    __shared__ float ybuf[CONV_DIM];
    __shared__ float norms[32];

    const int bt = blockIdx.x;
    const int b = bt >> 11;
    const int t = bt & 2047;
    const float keep = (input_pos[0] == 0) ? 0.f : 1.f;

    for (int c = threadIdx.x; c < CONV_DIM; c += 256) {
        float4 w = *(const float4*)&conv_w[c * 4];
        float in[4];
        #pragma unroll
        for (int j = 0; j < 4; j++) {
            int tau = t + j - 3;
            float v;
            if (tau >= 0) v = qkvz[((size_t)(b * TT + tau)) * QKVZ_N + c];
            else          v = keep * conv_state[((size_t)b * CONV_DIM + c) * 4 + (t + 1 + j)];
            in[j] = v;
        }
        float acc = in[0] * w.x + in[1] * w.y + in[2] * w.z + in[3] * w.w;
        float sig = 1.f / (1.f + expf(-acc));
        ybuf[c] = acc * sig;
    }
    __syncthreads();

    const int wid = threadIdx.x >> 5;
    const int lane = threadIdx.x & 31;
    for (int hh = wid; hh < 32; hh += 8) {
        int base = (hh < 16) ? hh * 128 : KEY_DIM + (hh - 16) * 128;
        float ss = 0.f;
        #pragma unroll
        for (int i = 0; i < 4; i++) {
            float v = ybuf[base + lane + i * 32];
            ss = fmaf(v, v, ss);
        }
        #pragma unroll
        for (int off = 16; off > 0; off >>= 1)
            ss += __shfl_xor_sync(0xffffffffu, ss, off);
        if (lane == 0) norms[hh] = fmaxf(sqrtf(ss), 1e-12f);
    }
    __syncthreads();

    float* yr = y_out + (size_t)bt * CONV_DIM;
    for (int c = threadIdx.x; c < CONV_DIM; c += 256) {
        float v = ybuf[c];
        if (c < 2 * KEY_DIM) v /= norms[c >> 7];
        yr[c] = v;
    }
}

// ---------------- gated linear-attention recurrence --------------------------
__global__ void __launch_bounds__(256)
recur_kernel(const float* __restrict__ y, const float* __restrict__ beta,
             const float* __restrict__ alpha, const float* __restrict__ rstate,
             const int* __restrict__ input_pos, float* __restrict__ att)
{
    __shared__ float qs[128], ks[128], vs[32];
    __shared__ float red[8][33];

    const int bh = blockIdx.y;
    const int b = bh >> 4, h = bh & 15;
    const int dvb = blockIdx.x * 32;
    const int tid = threadIdx.x;
    const int dvl = tid & 31;
    const int dkg = tid >> 5;
    const int dv = dvb + dvl;
    const float keep = (input_pos[0] == 0) ? 0.f : 1.f;

    float s[16];
    #pragma unroll
    for (int i = 0; i < 16; i++)
        s[i] = keep * rstate[((size_t)bh * 128 + (dkg * 16 + i)) * 128 + dv];

    const float* ybase = y + (size_t)b * TT * CONV_DIM + h * 128;
    const float* arow = alpha + (size_t)b * TT * HH + h;
    const float* brow = beta  + (size_t)b * TT * HH + h;

    for (int t = 0; t < TT; t++) {
        const float* yr = ybase + (size_t)t * CONV_DIM;
        if (tid < 128) qs[tid] = yr[tid];
        else           ks[tid - 128] = yr[KEY_DIM + (tid - 128)];
        if (tid < 32)  vs[tid] = yr[2 * KEY_DIM + dvb + tid];
        __syncthreads();

        float a = arow[(size_t)t * HH];
        float bta = brow[(size_t)t * HH];
        float bv = bta * vs[dvl];
        float po = 0.f;
        #pragma unroll
        for (int i = 0; i < 16; i++) {
            int dk = dkg * 16 + i;
            s[i] = fmaf(a, s[i], bv * ks[dk]);
            po = fmaf(qs[dk], s[i], po);
        }
        red[dkg][dvl] = po;
        __syncthreads();
        if (dkg == 0) {
            float o = 0.f;
            #pragma unroll
            for (int g = 0; g < 8; g++) o += red[g][dvl];
            att[((size_t)(b * TT + t)) * VALUE_DIM + h * 128 + dv] = o;
        }
    }
}

// ---------------- rmsnorm * norm_w * sigmoid(z) ------------------------------
__global__ void __launch_bounds__(256)
gate_kernel(const float* __restrict__ att, const float* __restrict__ qkvz,
            const float* __restrict__ norm_w, float* __restrict__ go)
{
    const int bt = blockIdx.x;
    const int wid = threadIdx.x >> 5;
    const int lane = threadIdx.x & 31;

    #pragma unroll
    for (int k = 0; k < 2; k++) {
        const int hh = wid * 2 + k;
        const float* ar = att + (size_t)bt * VALUE_DIM + hh * 128;
        float v[4];
        float ss = 0.f;
        #pragma unroll
        for (int i = 0; i < 4; i++) {
            v[i] = ar[lane + i * 32];
            ss = fmaf(v[i], v[i], ss);
        }
        #pragma unroll
        for (int off = 16; off > 0; off >>= 1)
            ss += __shfl_xor_sync(0xffffffffu, ss, off);
        float scale = rsqrtf(ss * (1.f / 128.f) + 1e-6f);
        const float* zr = qkvz + (size_t)bt * QKVZ_N + CONV_DIM + hh * 128;
        float* gr = go + (size_t)bt * VALUE_DIM + hh * 128;
        #pragma unroll
        for (int i = 0; i < 4; i++) {
            int dvi = lane + i * 32;
            float z = zr[dvi];
            float sig = 1.f / (1.f + expf(-z));
            gr[dvi] = v[i] * scale * norm_w[dvi] * sig;
        }
    }
}

// ---------------- launch -----------------------------------------------------
extern "C" void kernel_launch(void* const* d_in, const int* in_sizes, int n_in,
                              void* d_out, int out_size)
{
    const float* x          = (const float*)d_in[0];
    const int*   input_pos  = (const int*)  d_in[1];
    const float* W_qkvz     = (const float*)d_in[2];
    const float* W_b        = (const float*)d_in[3];
    const float* W_a        = (const float*)d_in[4];
    const float* conv_w     = (const float*)d_in[5];
    const float* norm_w     = (const float*)d_in[6];
    const float* W_out      = (const float*)d_in[7];
    const float* conv_state = (const float*)d_in[8];
    const float* rec_state  = (const float*)d_in[9];
    float* out = (float*)d_out;

    float *qkvz, *y, *beta, *alpha, *attb, *gob;
    cudaGetSymbolAddress((void**)&qkvz, g_qkvz);
    cudaGetSymbolAddress((void**)&y,    g_y);
    cudaGetSymbolAddress((void**)&beta, g_beta);
    cudaGetSymbolAddress((void**)&alpha,g_alpha);
    cudaGetSymbolAddress((void**)&attb, g_att);
    cudaGetSymbolAddress((void**)&gob,  g_go);

    // 1) qkvz = x @ W_qkvz      (4096 x 8192 x 2048), tf32 tensor cores
    tf32gemm<<<dim3(QKVZ_N / 256, BT / 128), 256>>>(x, W_qkvz, qkvz, BT, QKVZ_N, CC);
    // 2) beta/alpha
    ba_kernel<<<BT, 128>>>(x, W_b, W_a, beta, alpha);
    // 3) conv + silu + l2norm
    conv_kernel<<<BT, 256>>>(qkvz, conv_w, conv_state, input_pos, y);
    // 4) recurrence
    recur_kernel<<<dim3(4, 32), 256>>>(y, beta, alpha, rec_state, input_pos, attb);
    // 5) rmsnorm + gate
    gate_kernel<<<BT, 256>>>(attb, qkvz, norm_w, gob);
    // 6) out = gated @ W_out    (4096 x 2048 x 2048), tf32 tensor cores
    tf32gemm<<<dim3(CC / 256, BT / 128), 256>>>(gob, W_out, out, BT, CC, CC);
}

// round 7
// speedup vs baseline: 1.2696x; 1.2696x over previous
#include <cuda_runtime.h>
#include <cuda_fp16.h>
#include <math.h>
#include <stdint.h>

// Problem constants
#define BB 2
#define TT 2048
#define CC 2048
#define HH 16
#define KEY_DIM 2048
#define VALUE_DIM 2048
#define CONV_DIM 6144
#define QKVZ_N 8192
#define BT 4096   // B*T

// ---------------- scratch (static device globals; no allocation) -------------
__device__ float g_qkvz[(size_t)BT * QKVZ_N];   // 128 MiB
__device__ float g_y[(size_t)BT * CONV_DIM];    // 96 MiB
__device__ float g_beta[(size_t)BT * HH];
__device__ float g_alpha[(size_t)BT * HH];
__device__ float g_att[(size_t)BT * VALUE_DIM]; // 32 MiB
__device__ __half g_xh[(size_t)BT * CC];        // x in fp16
__device__ __half g_wqt[(size_t)QKVZ_N * CC];   // W_qkvz^T fp16 [N][K]
__device__ __half g_wot[(size_t)CC * CC];       // W_out^T fp16 [N][K]
__device__ __half g_goh[(size_t)BT * CC];       // gated output fp16

// ---------------- PTX helpers ------------------------------------------------
__device__ __forceinline__ uint32_t s2u(const void* p) {
    uint32_t a;
    asm("{ .reg .u64 t; cvta.to.shared.u64 t, %1; cvt.u32.u64 %0, t; }"
        : "=r"(a) : "l"(p));
    return a;
}
__device__ __forceinline__ void ldsm4(uint32_t* r, uint32_t addr) {
    asm volatile("ldmatrix.sync.aligned.m8n8.x4.shared.b16 {%0,%1,%2,%3}, [%4];"
                 : "=r"(r[0]), "=r"(r[1]), "=r"(r[2]), "=r"(r[3]) : "r"(addr));
}
__device__ __forceinline__ void mma168f16(float* d, const uint32_t* a,
                                          const uint32_t* b) {
    asm volatile(
        "mma.sync.aligned.m16n8k16.row.col.f32.f16.f16.f32 "
        "{%0,%1,%2,%3}, {%4,%5,%6,%7}, {%8,%9}, {%0,%1,%2,%3};\n"
        : "+f"(d[0]), "+f"(d[1]), "+f"(d[2]), "+f"(d[3])
        : "r"(a[0]), "r"(a[1]), "r"(a[2]), "r"(a[3]),
          "r"(b[0]), "r"(b[1]));
}

// ---------------- fp16 tensor-core GEMM --------------------------------------
// C[M,N] = A[M,K] * B^T, A fp16 row-major [M][K], B fp16 [N][K].
// CTA tile 128x256, BK=32, 256 threads, 8 warps (2x4), warp tile 64x64.
// Smem rows padded to 80B (32 halves + 16B pad) -> conflict-free ldmatrix.
// Double-buffered: stage = A(128x80=10240B) + B(256x80=20480B) = 30720B.
#define STAGE_B 30720
#define GEMM_SMEM (2 * STAGE_B)

__global__ void __launch_bounds__(256)
h16gemm(const __half* __restrict__ A, const __half* __restrict__ Bt,
        float* __restrict__ Cm, int M, int N, int Kd)
{
    extern __shared__ char smem[];
    const uint32_t sb = s2u(smem);
    const int tid  = threadIdx.x;
    const int bm   = blockIdx.y * 128;
    const int bn   = blockIdx.x * 256;
    const int lane = tid & 31;
    const int warp = tid >> 5;
    const int wm   = (warp >> 2) * 64;
    const int wn   = (warp & 3) * 64;
    const int gid  = lane >> 2;
    const int tig  = lane & 3;

    // loader: chunk = 16B = 8 halves. A: rows r, r+64; B: rows r..r+192.
    const int lr = tid >> 2;            // 0..63
    const int lc = tid & 3;             // k-chunk 0..3

    const __half* Ap = A  + (size_t)(bm + lr) * Kd + lc * 8;
    const __half* Bp = Bt + (size_t)(bn + lr) * Kd + lc * 8;
    const size_t a64 = (size_t)64 * Kd;

    float acc[4][8][4];
    #pragma unroll
    for (int i = 0; i < 4; i++)
        #pragma unroll
        for (int j = 0; j < 8; j++)
            #pragma unroll
            for (int r = 0; r < 4; r++) acc[i][j][r] = 0.f;

    // prologue: load + store stage 0
    {
        uint4 ra0 = *(const uint4*)Ap;
        uint4 ra1 = *(const uint4*)(Ap + a64);
        uint4 rb0 = *(const uint4*)Bp;
        uint4 rb1 = *(const uint4*)(Bp + a64);
        uint4 rb2 = *(const uint4*)(Bp + 2 * a64);
        uint4 rb3 = *(const uint4*)(Bp + 3 * a64);
        char* s0 = smem;
        *(uint4*)(s0 + lr * 80 + lc * 16)        = ra0;
        *(uint4*)(s0 + (lr + 64) * 80 + lc * 16) = ra1;
        char* s0b = s0 + 10240;
        *(uint4*)(s0b + lr * 80 + lc * 16)         = rb0;
        *(uint4*)(s0b + (lr + 64) * 80 + lc * 16)  = rb1;
        *(uint4*)(s0b + (lr + 128) * 80 + lc * 16) = rb2;
        *(uint4*)(s0b + (lr + 192) * 80 + lc * 16) = rb3;
    }
    __syncthreads();

    // fragment-read lane geometry
    const int at = lane >> 3;                   // tile id 0..3
    const int arow = wm + (at & 1) * 8 + (lane & 7);
    const int akoff = (lane >> 4) * 16;         // chunk offset within ks pair
    const int brow = wn + (lane >> 4) * 8 + (lane & 7);
    const int bkoff = ((lane >> 3) & 1) * 16;

    const int nst = Kd / 32;
    for (int s = 0; s < nst; s++) {
        const bool more = (s + 1) < nst;
        uint4 ra0, ra1, rb0, rb1, rb2, rb3;
        if (more) {
            Ap += 32; Bp += 32;
            ra0 = *(const uint4*)Ap;
            ra1 = *(const uint4*)(Ap + a64);
            rb0 = *(const uint4*)Bp;
            rb1 = *(const uint4*)(Bp + a64);
            rb2 = *(const uint4*)(Bp + 2 * a64);
            rb3 = *(const uint4*)(Bp + 3 * a64);
        }

        const uint32_t base = sb + (uint32_t)(s & 1) * STAGE_B;
        #pragma unroll
        for (int ks = 0; ks < 2; ks++) {
            uint32_t aF[4][4], bF[4][4];
            const uint32_t ak = base + (uint32_t)(ks * 32 + akoff);
            #pragma unroll
            for (int mt = 0; mt < 4; mt++)
                ldsm4(aF[mt], ak + (uint32_t)(arow + mt * 16) * 80);
            const uint32_t bk = base + 10240u + (uint32_t)(ks * 32 + bkoff);
            #pragma unroll
            for (int np = 0; np < 4; np++)
                ldsm4(bF[np], bk + (uint32_t)(brow + np * 16) * 80);
            #pragma unroll
            for (int mt = 0; mt < 4; mt++)
                #pragma unroll
                for (int nt = 0; nt < 8; nt++)
                    mma168f16(acc[mt][nt], aF[mt], &bF[nt >> 1][(nt & 1) * 2]);
        }

        if (more) {
            char* sn = smem + ((s + 1) & 1) * STAGE_B;
            *(uint4*)(sn + lr * 80 + lc * 16)        = ra0;
            *(uint4*)(sn + (lr + 64) * 80 + lc * 16) = ra1;
            char* snb = sn + 10240;
            *(uint4*)(snb + lr * 80 + lc * 16)         = rb0;
            *(uint4*)(snb + (lr + 64) * 80 + lc * 16)  = rb1;
            *(uint4*)(snb + (lr + 128) * 80 + lc * 16) = rb2;
            *(uint4*)(snb + (lr + 192) * 80 + lc * 16) = rb3;
        }
        __syncthreads();
    }

    #pragma unroll
    for (int mt = 0; mt < 4; mt++) {
        const int row = bm + wm + mt * 16 + gid;
        #pragma unroll
        for (int nt = 0; nt < 8; nt++) {
            const int col = bn + wn + nt * 8 + 2 * tig;
            *(float2*)&Cm[(size_t)row * N + col]       = make_float2(acc[mt][nt][0], acc[mt][nt][1]);
            *(float2*)&Cm[(size_t)(row + 8) * N + col] = make_float2(acc[mt][nt][2], acc[mt][nt][3]);
        }
    }
}

// ---------------- f32 -> f16 convert -----------------------------------------
__global__ void __launch_bounds__(256)
to_half(const float* __restrict__ X, __half* __restrict__ Y, int n8)
{
    int i = blockIdx.x * 256 + threadIdx.x;
    if (i >= n8) return;
    float4 v0 = ((const float4*)X)[i * 2];
    float4 v1 = ((const float4*)X)[i * 2 + 1];
    __half2* H = (__half2*)Y;
    H[i * 4 + 0] = __floats2half2_rn(v0.x, v0.y);
    H[i * 4 + 1] = __floats2half2_rn(v0.z, v0.w);
    H[i * 4 + 2] = __floats2half2_rn(v1.x, v1.y);
    H[i * 4 + 3] = __floats2half2_rn(v1.z, v1.w);
}

// ---------------- transpose: W[K][N] f32 -> Wt[N][K] f16 ---------------------
__global__ void __launch_bounds__(256)
transpose_half(const float* __restrict__ W, __half* __restrict__ Th, int K, int N)
{
    __shared__ float tile[32][33];
    const int k0 = blockIdx.y * 32, n0 = blockIdx.x * 32;
    const int tx = threadIdx.x & 31, ty = threadIdx.x >> 5;   // 32x8
    #pragma unroll
    for (int r = 0; r < 32; r += 8)
        tile[ty + r][tx] = W[(size_t)(k0 + ty + r) * N + n0 + tx];
    __syncthreads();
    #pragma unroll
    for (int r = 0; r < 32; r += 8)
        Th[(size_t)(n0 + ty + r) * K + k0 + tx] = __float2half(tile[tx][ty + r]);
}

// ---------------- beta/alpha: sigmoid(x @ W_b), sigmoid(x @ W_a) -------------
__global__ void __launch_bounds__(128)
ba_kernel(const float* __restrict__ x, const float* __restrict__ Wb,
          const float* __restrict__ Wa, float* __restrict__ beta,
          float* __restrict__ alpha)
{
    __shared__ float xs[CC];
    const int row = blockIdx.x;
    const float* xr = x + (size_t)row * CC;
    for (int i = threadIdx.x; i < CC; i += 128) xs[i] = xr[i];
    __syncthreads();

    const int g = threadIdx.x >> 2;
    const int l = threadIdx.x & 3;
    const float* W = (g < 16) ? Wb : Wa;
    const int h = g & 15;
    float s = 0.f;
    for (int cidx = l; cidx < CC; cidx += 4)
        s = fmaf(xs[cidx], W[cidx * HH + h], s);
    s += __shfl_down_sync(0xffffffffu, s, 2);
    s += __shfl_down_sync(0xffffffffu, s, 1);
    if (l == 0) {
        float v = 1.f / (1.f + expf(-s));
        if (g < 16) beta[(size_t)row * HH + h] = v;
        else        alpha[(size_t)row * HH + h] = v;
    }
}

// ---------------- causal depthwise conv(K=4) + silu + l2norm of q,k ----------
__global__ void __launch_bounds__(256)
conv_kernel(const float* __restrict__ qkvz, const float* __restrict__ conv_w,
            const float* __restrict__ conv_state, const int* __restrict__ input_pos,
            float* __restrict__ y_out)
{
    __shared__ float ybuf[CONV_DIM];
    __shared__ float norms[32];

    const int bt = blockIdx.x;
    const int b = bt >> 11;
    const int t = bt & 2047;
    const float keep = (input_pos[0] == 0) ? 0.f : 1.f;

    for (int c = threadIdx.x; c < CONV_DIM; c += 256) {
        float4 w = *(const float4*)&conv_w[c * 4];
        float in[4];
        #pragma unroll
        for (int j = 0; j < 4; j++) {
            int tau = t + j - 3;
            float v;
            if (tau >= 0) v = qkvz[((size_t)(b * TT + tau)) * QKVZ_N + c];
            else          v = keep * conv_state[((size_t)b * CONV_DIM + c) * 4 + (t + 1 + j)];
            in[j] = v;
        }
        float acc = in[0] * w.x + in[1] * w.y + in[2] * w.z + in[3] * w.w;
        float sig = 1.f / (1.f + expf(-acc));
        ybuf[c] = acc * sig;
    }
    __syncthreads();

    const int wid = threadIdx.x >> 5;
    const int lane = threadIdx.x & 31;
    for (int hh = wid; hh < 32; hh += 8) {
        int base = (hh < 16) ? hh * 128 : KEY_DIM + (hh - 16) * 128;
        float ss = 0.f;
        #pragma unroll
        for (int i = 0; i < 4; i++) {
            float v = ybuf[base + lane + i * 32];
            ss = fmaf(v, v, ss);
        }
        #pragma unroll
        for (int off = 16; off > 0; off >>= 1)
            ss += __shfl_xor_sync(0xffffffffu, ss, off);
        if (lane == 0) norms[hh] = fmaxf(sqrtf(ss), 1e-12f);
    }
    __syncthreads();

    float* yr = y_out + (size_t)bt * CONV_DIM;
    for (int c = threadIdx.x; c < CONV_DIM; c += 256) {
        float v = ybuf[c];
        if (c < 2 * KEY_DIM) v /= norms[c >> 7];
        yr[c] = v;
    }
}

// ---------------- gated linear-attention recurrence --------------------------
__global__ void __launch_bounds__(256)
recur_kernel(const float* __restrict__ y, const float* __restrict__ beta,
             const float* __restrict__ alpha, const float* __restrict__ rstate,
             const int* __restrict__ input_pos, float* __restrict__ att)
{
    __shared__ float qs[128], ks[128], vs[32];
    __shared__ float red[8][33];

    const int bh = blockIdx.y;
    const int b = bh >> 4, h = bh & 15;
    const int dvb = blockIdx.x * 32;
    const int tid = threadIdx.x;
    const int dvl = tid & 31;
    const int dkg = tid >> 5;
    const int dv = dvb + dvl;
    const float keep = (input_pos[0] == 0) ? 0.f : 1.f;

    float s[16];
    #pragma unroll
    for (int i = 0; i < 16; i++)
        s[i] = keep * rstate[((size_t)bh * 128 + (dkg * 16 + i)) * 128 + dv];

    const float* ybase = y + (size_t)b * TT * CONV_DIM + h * 128;
    const float* arow = alpha + (size_t)b * TT * HH + h;
    const float* brow = beta  + (size_t)b * TT * HH + h;

    for (int t = 0; t < TT; t++) {
        const float* yr = ybase + (size_t)t * CONV_DIM;
        if (tid < 128) qs[tid] = yr[tid];
        else           ks[tid - 128] = yr[KEY_DIM + (tid - 128)];
        if (tid < 32)  vs[tid] = yr[2 * KEY_DIM + dvb + tid];
        __syncthreads();

        float a = arow[(size_t)t * HH];
        float bta = brow[(size_t)t * HH];
        float bv = bta * vs[dvl];
        float po = 0.f;
        #pragma unroll
        for (int i = 0; i < 16; i++) {
            int dk = dkg * 16 + i;
            s[i] = fmaf(a, s[i], bv * ks[dk]);
            po = fmaf(qs[dk], s[i], po);
        }
        red[dkg][dvl] = po;
        __syncthreads();
        if (dkg == 0) {
            float o = 0.f;
            #pragma unroll
            for (int g = 0; g < 8; g++) o += red[g][dvl];
            att[((size_t)(b * TT + t)) * VALUE_DIM + h * 128 + dv] = o;
        }
    }
}

// ---------------- rmsnorm * norm_w * sigmoid(z) -> fp16 ----------------------
__global__ void __launch_bounds__(256)
gate_kernel(const float* __restrict__ att, const float* __restrict__ qkvz,
            const float* __restrict__ norm_w, __half* __restrict__ goh)
{
    const int bt = blockIdx.x;
    const int wid = threadIdx.x >> 5;
    const int lane = threadIdx.x & 31;

    #pragma unroll
    for (int k = 0; k < 2; k++) {
        const int hh = wid * 2 + k;
        const float* ar = att + (size_t)bt * VALUE_DIM + hh * 128;
        float v[4];
        float ss = 0.f;
        #pragma unroll
        for (int i = 0; i < 4; i++) {
            v[i] = ar[lane + i * 32];
            ss = fmaf(v[i], v[i], ss);
        }
        #pragma unroll
        for (int off = 16; off > 0; off >>= 1)
            ss += __shfl_xor_sync(0xffffffffu, ss, off);
        float scale = rsqrtf(ss * (1.f / 128.f) + 1e-6f);
        const float* zr = qkvz + (size_t)bt * QKVZ_N + CONV_DIM + hh * 128;
        __half* gr = goh + (size_t)bt * VALUE_DIM + hh * 128;
        #pragma unroll
        for (int i = 0; i < 4; i++) {
            int dvi = lane + i * 32;
            float z = zr[dvi];
            float sig = 1.f / (1.f + expf(-z));
            gr[dvi] = __float2half(v[i] * scale * norm_w[dvi] * sig);
        }
    }
}

// ---------------- launch -----------------------------------------------------
extern "C" void kernel_launch(void* const* d_in, const int* in_sizes, int n_in,
                              void* d_out, int out_size)
{
    const float* x          = (const float*)d_in[0];
    const int*   input_pos  = (const int*)  d_in[1];
    const float* W_qkvz     = (const float*)d_in[2];
    const float* W_b        = (const float*)d_in[3];
    const float* W_a        = (const float*)d_in[4];
    const float* conv_w     = (const float*)d_in[5];
    const float* norm_w     = (const float*)d_in[6];
    const float* W_out      = (const float*)d_in[7];
    const float* conv_state = (const float*)d_in[8];
    const float* rec_state  = (const float*)d_in[9];
    float* out = (float*)d_out;

    float *qkvz, *y, *beta, *alpha, *attb;
    __half *xh, *wqt, *wot, *goh;
    cudaGetSymbolAddress((void**)&qkvz, g_qkvz);
    cudaGetSymbolAddress((void**)&y,    g_y);
    cudaGetSymbolAddress((void**)&beta, g_beta);
    cudaGetSymbolAddress((void**)&alpha,g_alpha);
    cudaGetSymbolAddress((void**)&attb, g_att);
    cudaGetSymbolAddress((void**)&xh,  g_xh);
    cudaGetSymbolAddress((void**)&wqt, g_wqt);
    cudaGetSymbolAddress((void**)&wot, g_wot);
    cudaGetSymbolAddress((void**)&goh, g_goh);

    cudaFuncSetAttribute(h16gemm, cudaFuncAttributeMaxDynamicSharedMemorySize,
                         GEMM_SMEM);

    // 0) operand prep
    to_half<<<(BT * CC / 8 + 255) / 256, 256>>>(x, xh, BT * CC / 8);
    transpose_half<<<dim3(QKVZ_N / 32, CC / 32), 256>>>(W_qkvz, wqt, CC, QKVZ_N);
    transpose_half<<<dim3(CC / 32, CC / 32), 256>>>(W_out, wot, CC, CC);

    // 1) qkvz = x @ W_qkvz  (fp16 mma.m16n8k16)
    h16gemm<<<dim3(QKVZ_N / 256, BT / 128), 256, GEMM_SMEM>>>(
        xh, wqt, qkvz, BT, QKVZ_N, CC);
    // 2) beta/alpha
    ba_kernel<<<BT, 128>>>(x, W_b, W_a, beta, alpha);
    // 3) conv + silu + l2norm
    conv_kernel<<<BT, 256>>>(qkvz, conv_w, conv_state, input_pos, y);
    // 4) recurrence
    recur_kernel<<<dim3(4, 32), 256>>>(y, beta, alpha, rec_state, input_pos, attb);
    // 5) rmsnorm + gate -> fp16
    gate_kernel<<<BT, 256>>>(attb, qkvz, norm_w, goh);
    // 6) out = gated @ W_out  (fp16 mma.m16n8k16)
    h16gemm<<<dim3(CC / 256, BT / 128), 256, GEMM_SMEM>>>(
        goh, wot, out, BT, CC, CC);
}

// round 8
// speedup vs baseline: 1.7558x; 1.3829x over previous
#include <cuda_runtime.h>
#include <cuda_fp16.h>
#include <math.h>
#include <stdint.h>

// Problem constants
#define BB 2
#define TT 2048
#define CC 2048
#define HH 16
#define KEY_DIM 2048
#define VALUE_DIM 2048
#define CONV_DIM 6144
#define QKVZ_N 8192
#define BT 4096   // B*T

// ---------------- scratch (static device globals; no allocation) -------------
__device__ float g_qkvz[(size_t)BT * QKVZ_N];   // 128 MiB
__device__ float g_y[(size_t)BT * CONV_DIM];    // 96 MiB
__device__ float g_beta[(size_t)BT * HH];
__device__ float g_alpha[(size_t)BT * HH];
__device__ float g_att[(size_t)BT * VALUE_DIM]; // 32 MiB
__device__ __half g_xh[(size_t)BT * CC];        // x in fp16
__device__ __half g_wqt[(size_t)QKVZ_N * CC];   // W_qkvz^T fp16 [N][K]
__device__ __half g_wot[(size_t)CC * CC];       // W_out^T fp16 [N][K]
__device__ __half g_goh[(size_t)BT * CC];       // gated output fp16

// ---------------- PTX helpers ------------------------------------------------
__device__ __forceinline__ uint32_t s2u(const void* p) {
    uint32_t a;
    asm("{ .reg .u64 t; cvta.to.shared.u64 t, %1; cvt.u32.u64 %0, t; }"
        : "=r"(a) : "l"(p));
    return a;
}
__device__ __forceinline__ void ldsm4(uint32_t* r, uint32_t addr) {
    asm volatile("ldmatrix.sync.aligned.m8n8.x4.shared.b16 {%0,%1,%2,%3}, [%4];"
                 : "=r"(r[0]), "=r"(r[1]), "=r"(r[2]), "=r"(r[3]) : "r"(addr));
}
__device__ __forceinline__ void mma168f16(float* d, const uint32_t* a,
                                          const uint32_t* b) {
    asm volatile(
        "mma.sync.aligned.m16n8k16.row.col.f32.f16.f16.f32 "
        "{%0,%1,%2,%3}, {%4,%5,%6,%7}, {%8,%9}, {%0,%1,%2,%3};\n"
        : "+f"(d[0]), "+f"(d[1]), "+f"(d[2]), "+f"(d[3])
        : "r"(a[0]), "r"(a[1]), "r"(a[2]), "r"(a[3]),
          "r"(b[0]), "r"(b[1]));
}
__device__ __forceinline__ void cpasync16(uint32_t dst, const void* src) {
    asm volatile("cp.async.ca.shared.global [%0], [%1], 16;"
                 :: "r"(dst), "l"(src));
}
__device__ __forceinline__ void cpasync4(uint32_t dst, const void* src) {
    asm volatile("cp.async.ca.shared.global [%0], [%1], 4;"
                 :: "r"(dst), "l"(src));
}
__device__ __forceinline__ void cp_commit() {
    asm volatile("cp.async.commit_group;");
}
__device__ __forceinline__ void cp_wait1() {
    asm volatile("cp.async.wait_group 1;" ::: "memory");
}
__device__ __forceinline__ void cp_wait0() {
    asm volatile("cp.async.wait_group 0;" ::: "memory");
}

// ---------------- fp16 tensor-core GEMM --------------------------------------
// C[M,N] = A[M,K] * B^T, A fp16 row-major [M][K], B fp16 [N][K].
// CTA tile 128x256, BK=32, 256 threads, 8 warps (2x4), warp tile 64x64.
// Smem rows padded to 80B; double-buffered (register-staged loads).
#define STAGE_B 30720
#define GEMM_SMEM (2 * STAGE_B)

__global__ void __launch_bounds__(256)
h16gemm(const __half* __restrict__ A, const __half* __restrict__ Bt,
        float* __restrict__ Cm, int M, int N, int Kd)
{
    extern __shared__ char smem[];
    const uint32_t sb = s2u(smem);
    const int tid  = threadIdx.x;
    const int bm   = blockIdx.y * 128;
    const int bn   = blockIdx.x * 256;
    const int lane = tid & 31;
    const int warp = tid >> 5;
    const int wm   = (warp >> 2) * 64;
    const int wn   = (warp & 3) * 64;
    const int gid  = lane >> 2;
    const int tig  = lane & 3;

    const int lr = tid >> 2;            // 0..63
    const int lc = tid & 3;             // k-chunk 0..3

    const __half* Ap = A  + (size_t)(bm + lr) * Kd + lc * 8;
    const __half* Bp = Bt + (size_t)(bn + lr) * Kd + lc * 8;
    const size_t a64 = (size_t)64 * Kd;

    float acc[4][8][4];
    #pragma unroll
    for (int i = 0; i < 4; i++)
        #pragma unroll
        for (int j = 0; j < 8; j++)
            #pragma unroll
            for (int r = 0; r < 4; r++) acc[i][j][r] = 0.f;

    {
        uint4 ra0 = *(const uint4*)Ap;
        uint4 ra1 = *(const uint4*)(Ap + a64);
        uint4 rb0 = *(const uint4*)Bp;
        uint4 rb1 = *(const uint4*)(Bp + a64);
        uint4 rb2 = *(const uint4*)(Bp + 2 * a64);
        uint4 rb3 = *(const uint4*)(Bp + 3 * a64);
        char* s0 = smem;
        *(uint4*)(s0 + lr * 80 + lc * 16)        = ra0;
        *(uint4*)(s0 + (lr + 64) * 80 + lc * 16) = ra1;
        char* s0b = s0 + 10240;
        *(uint4*)(s0b + lr * 80 + lc * 16)         = rb0;
        *(uint4*)(s0b + (lr + 64) * 80 + lc * 16)  = rb1;
        *(uint4*)(s0b + (lr + 128) * 80 + lc * 16) = rb2;
        *(uint4*)(s0b + (lr + 192) * 80 + lc * 16) = rb3;
    }
    __syncthreads();

    const int at = lane >> 3;
    const int arow = wm + (at & 1) * 8 + (lane & 7);
    const int akoff = (lane >> 4) * 16;
    const int brow = wn + (lane >> 4) * 8 + (lane & 7);
    const int bkoff = ((lane >> 3) & 1) * 16;

    const int nst = Kd / 32;
    for (int s = 0; s < nst; s++) {
        const bool more = (s + 1) < nst;
        uint4 ra0, ra1, rb0, rb1, rb2, rb3;
        if (more) {
            Ap += 32; Bp += 32;
            ra0 = *(const uint4*)Ap;
            ra1 = *(const uint4*)(Ap + a64);
            rb0 = *(const uint4*)Bp;
            rb1 = *(const uint4*)(Bp + a64);
            rb2 = *(const uint4*)(Bp + 2 * a64);
            rb3 = *(const uint4*)(Bp + 3 * a64);
        }

        const uint32_t base = sb + (uint32_t)(s & 1) * STAGE_B;
        #pragma unroll
        for (int ks = 0; ks < 2; ks++) {
            uint32_t aF[4][4], bF[4][4];
            const uint32_t ak = base + (uint32_t)(ks * 32 + akoff);
            #pragma unroll
            for (int mt = 0; mt < 4; mt++)
                ldsm4(aF[mt], ak + (uint32_t)(arow + mt * 16) * 80);
            const uint32_t bk = base + 10240u + (uint32_t)(ks * 32 + bkoff);
            #pragma unroll
            for (int np = 0; np < 4; np++)
                ldsm4(bF[np], bk + (uint32_t)(brow + np * 16) * 80);
            #pragma unroll
            for (int mt = 0; mt < 4; mt++)
                #pragma unroll
                for (int nt = 0; nt < 8; nt++)
                    mma168f16(acc[mt][nt], aF[mt], &bF[nt >> 1][(nt & 1) * 2]);
        }

        if (more) {
            char* sn = smem + ((s + 1) & 1) * STAGE_B;
            *(uint4*)(sn + lr * 80 + lc * 16)        = ra0;
            *(uint4*)(sn + (lr + 64) * 80 + lc * 16) = ra1;
            char* snb = sn + 10240;
            *(uint4*)(snb + lr * 80 + lc * 16)         = rb0;
            *(uint4*)(snb + (lr + 64) * 80 + lc * 16)  = rb1;
            *(uint4*)(snb + (lr + 128) * 80 + lc * 16) = rb2;
            *(uint4*)(snb + (lr + 192) * 80 + lc * 16) = rb3;
        }
        __syncthreads();
    }

    #pragma unroll
    for (int mt = 0; mt < 4; mt++) {
        const int row = bm + wm + mt * 16 + gid;
        #pragma unroll
        for (int nt = 0; nt < 8; nt++) {
            const int col = bn + wn + nt * 8 + 2 * tig;
            *(float2*)&Cm[(size_t)row * N + col]       = make_float2(acc[mt][nt][0], acc[mt][nt][1]);
            *(float2*)&Cm[(size_t)(row + 8) * N + col] = make_float2(acc[mt][nt][2], acc[mt][nt][3]);
        }
    }
}

// ---------------- f32 -> f16 convert -----------------------------------------
__global__ void __launch_bounds__(256)
to_half(const float* __restrict__ X, __half* __restrict__ Y, int n8)
{
    int i = blockIdx.x * 256 + threadIdx.x;
    if (i >= n8) return;
    float4 v0 = ((const float4*)X)[i * 2];
    float4 v1 = ((const float4*)X)[i * 2 + 1];
    __half2* H = (__half2*)Y;
    H[i * 4 + 0] = __floats2half2_rn(v0.x, v0.y);
    H[i * 4 + 1] = __floats2half2_rn(v0.z, v0.w);
    H[i * 4 + 2] = __floats2half2_rn(v1.x, v1.y);
    H[i * 4 + 3] = __floats2half2_rn(v1.z, v1.w);
}

// ---------------- transpose: W[K][N] f32 -> Wt[N][K] f16 ---------------------
__global__ void __launch_bounds__(256)
transpose_half(const float* __restrict__ W, __half* __restrict__ Th, int K, int N)
{
    __shared__ float tile[32][33];
    const int k0 = blockIdx.y * 32, n0 = blockIdx.x * 32;
    const int tx = threadIdx.x & 31, ty = threadIdx.x >> 5;
    #pragma unroll
    for (int r = 0; r < 32; r += 8)
        tile[ty + r][tx] = W[(size_t)(k0 + ty + r) * N + n0 + tx];
    __syncthreads();
    #pragma unroll
    for (int r = 0; r < 32; r += 8)
        Th[(size_t)(n0 + ty + r) * K + k0 + tx] = __float2half(tile[tx][ty + r]);
}

// ---------------- beta/alpha: sigmoid(x @ W_b), sigmoid(x @ W_a) -------------
__global__ void __launch_bounds__(128)
ba_kernel(const float* __restrict__ x, const float* __restrict__ Wb,
          const float* __restrict__ Wa, float* __restrict__ beta,
          float* __restrict__ alpha)
{
    __shared__ float xs[CC];
    const int row = blockIdx.x;
    const float* xr = x + (size_t)row * CC;
    for (int i = threadIdx.x; i < CC; i += 128) xs[i] = xr[i];
    __syncthreads();

    const int g = threadIdx.x >> 2;
    const int l = threadIdx.x & 3;
    const float* W = (g < 16) ? Wb : Wa;
    const int h = g & 15;
    float s = 0.f;
    for (int cidx = l; cidx < CC; cidx += 4)
        s = fmaf(xs[cidx], W[cidx * HH + h], s);
    s += __shfl_down_sync(0xffffffffu, s, 2);
    s += __shfl_down_sync(0xffffffffu, s, 1);
    if (l == 0) {
        float v = 1.f / (1.f + expf(-s));
        if (g < 16) beta[(size_t)row * HH + h] = v;
        else        alpha[(size_t)row * HH + h] = v;
    }
}

// ---------------- causal depthwise conv(K=4) + silu + l2norm of q,k ----------
__global__ void __launch_bounds__(256)
conv_kernel(const float* __restrict__ qkvz, const float* __restrict__ conv_w,
            const float* __restrict__ conv_state, const int* __restrict__ input_pos,
            float* __restrict__ y_out)
{
    __shared__ float ybuf[CONV_DIM];
    __shared__ float norms[32];

    const int bt = blockIdx.x;
    const int b = bt >> 11;
    const int t = bt & 2047;
    const float keep = (input_pos[0] == 0) ? 0.f : 1.f;

    for (int c = threadIdx.x; c < CONV_DIM; c += 256) {
        float4 w = *(const float4*)&conv_w[c * 4];
        float in[4];
        #pragma unroll
        for (int j = 0; j < 4; j++) {
            int tau = t + j - 3;
            float v;
            if (tau >= 0) v = qkvz[((size_t)(b * TT + tau)) * QKVZ_N + c];
            else          v = keep * conv_state[((size_t)b * CONV_DIM + c) * 4 + (t + 1 + j)];
            in[j] = v;
        }
        float acc = in[0] * w.x + in[1] * w.y + in[2] * w.z + in[3] * w.w;
        float sig = 1.f / (1.f + expf(-acc));
        ybuf[c] = acc * sig;
    }
    __syncthreads();

    const int wid = threadIdx.x >> 5;
    const int lane = threadIdx.x & 31;
    for (int hh = wid; hh < 32; hh += 8) {
        int base = (hh < 16) ? hh * 128 : KEY_DIM + (hh - 16) * 128;
        float ss = 0.f;
        #pragma unroll
        for (int i = 0; i < 4; i++) {
            float v = ybuf[base + lane + i * 32];
            ss = fmaf(v, v, ss);
        }
        #pragma unroll
        for (int off = 16; off > 0; off >>= 1)
            ss += __shfl_xor_sync(0xffffffffu, ss, off);
        if (lane == 0) norms[hh] = fmaxf(sqrtf(ss), 1e-12f);
    }
    __syncthreads();

    float* yr = y_out + (size_t)bt * CONV_DIM;
    for (int c = threadIdx.x; c < CONV_DIM; c += 256) {
        float v = ybuf[c];
        if (c < 2 * KEY_DIM) v /= norms[c >> 7];
        yr[c] = v;
    }
}

// ---------------- gated linear-attention recurrence --------------------------
// grid (4, 32). cp.async double-buffered prefetch of (q,k,v,a,b) per step:
// step t computes from buf[t&1] while t+1 streams into buf[(t+1)&1].
__global__ void __launch_bounds__(256)
recur_kernel(const float* __restrict__ y, const float* __restrict__ beta,
             const float* __restrict__ alpha, const float* __restrict__ rstate,
             const int* __restrict__ input_pos, float* __restrict__ att)
{
    // per buffer: q[0..127], k[128..255], v[256..287], a@288, b@289 (pad 292)
    __shared__ float buf[2][292];
    __shared__ float red[8][33];

    const int bh = blockIdx.y;
    const int b = bh >> 4, h = bh & 15;
    const int dvb = blockIdx.x * 32;
    const int tid = threadIdx.x;
    const int dvl = tid & 31;
    const int dkg = tid >> 5;
    const int dv = dvb + dvl;
    const float keep = (input_pos[0] == 0) ? 0.f : 1.f;
    const uint32_t sb = s2u(&buf[0][0]);

    float s[16];
    #pragma unroll
    for (int i = 0; i < 16; i++)
        s[i] = keep * rstate[((size_t)bh * 128 + (dkg * 16 + i)) * 128 + dv];

    const float* ybase = y + (size_t)b * TT * CONV_DIM + h * 128;
    const float* arow = alpha + (size_t)b * TT * HH + h;
    const float* brow = beta  + (size_t)b * TT * HH + h;

    // prefetch issue helper geometry (each 16B chunk = 4 floats)
    // threads 0..31: q chunk tid; 32..63: k; 64..71: v; 72: a; 73: b
    auto issue = [&](int t, int bi) {
        const uint32_t dst = sb + (uint32_t)bi * (292 * 4);
        const float* yr = ybase + (size_t)t * CONV_DIM;
        if (tid < 32) {
            cpasync16(dst + tid * 16, yr + tid * 4);
        } else if (tid < 64) {
            cpasync16(dst + tid * 16, yr + KEY_DIM + (tid - 32) * 4);
        } else if (tid < 72) {
            cpasync16(dst + 256 * 4 + (tid - 64) * 16, yr + 2 * KEY_DIM + dvb + (tid - 64) * 4);
        } else if (tid == 72) {
            cpasync4(dst + 288 * 4, arow + (size_t)t * HH);
        } else if (tid == 73) {
            cpasync4(dst + 289 * 4, brow + (size_t)t * HH);
        }
        cp_commit();
    };

    issue(0, 0);

    for (int t = 0; t < TT; t++) {
        const int cb = t & 1;
        if (t + 1 < TT) { issue(t + 1, cb ^ 1); cp_wait1(); }
        else            { cp_wait0(); }
        __syncthreads();

        const float a   = buf[cb][288];
        const float bta = buf[cb][289];
        const float bv  = bta * buf[cb][256 + dvl];
        const float* qs = &buf[cb][0];
        const float* ks = &buf[cb][128];
        float po0 = 0.f, po1 = 0.f;
        #pragma unroll
        for (int i = 0; i < 8; i++) {
            int dk = dkg * 16 + i;
            s[i] = fmaf(a, s[i], bv * ks[dk]);
            po0 = fmaf(qs[dk], s[i], po0);
        }
        #pragma unroll
        for (int i = 8; i < 16; i++) {
            int dk = dkg * 16 + i;
            s[i] = fmaf(a, s[i], bv * ks[dk]);
            po1 = fmaf(qs[dk], s[i], po1);
        }
        red[dkg][dvl] = po0 + po1;
        __syncthreads();        // also protects buf[cb^1]->buf[cb] reuse
        if (dkg == 0) {
            float o = 0.f;
            #pragma unroll
            for (int g = 0; g < 8; g++) o += red[g][dvl];
            att[((size_t)(b * TT + t)) * VALUE_DIM + h * 128 + dv] = o;
        }
    }
}

// ---------------- rmsnorm * norm_w * sigmoid(z) -> fp16 ----------------------
__global__ void __launch_bounds__(256)
gate_kernel(const float* __restrict__ att, const float* __restrict__ qkvz,
            const float* __restrict__ norm_w, __half* __restrict__ goh)
{
    const int bt = blockIdx.x;
    const int wid = threadIdx.x >> 5;
    const int lane = threadIdx.x & 31;

    #pragma unroll
    for (int k = 0; k < 2; k++) {
        const int hh = wid * 2 + k;
        const float* ar = att + (size_t)bt * VALUE_DIM + hh * 128;
        float v[4];
        float ss = 0.f;
        #pragma unroll
        for (int i = 0; i < 4; i++) {
            v[i] = ar[lane + i * 32];
            ss = fmaf(v[i], v[i], ss);
        }
        #pragma unroll
        for (int off = 16; off > 0; off >>= 1)
            ss += __shfl_xor_sync(0xffffffffu, ss, off);
        float scale = rsqrtf(ss * (1.f / 128.f) + 1e-6f);
        const float* zr = qkvz + (size_t)bt * QKVZ_N + CONV_DIM + hh * 128;
        __half* gr = goh + (size_t)bt * VALUE_DIM + hh * 128;
        #pragma unroll
        for (int i = 0; i < 4; i++) {
            int dvi = lane + i * 32;
            float z = zr[dvi];
            float sig = 1.f / (1.f + expf(-z));
            gr[dvi] = __float2half(v[i] * scale * norm_w[dvi] * sig);
        }
    }
}

// ---------------- launch -----------------------------------------------------
extern "C" void kernel_launch(void* const* d_in, const int* in_sizes, int n_in,
                              void* d_out, int out_size)
{
    const float* x          = (const float*)d_in[0];
    const int*   input_pos  = (const int*)  d_in[1];
    const float* W_qkvz     = (const float*)d_in[2];
    const float* W_b        = (const float*)d_in[3];
    const float* W_a        = (const float*)d_in[4];
    const float* conv_w     = (const float*)d_in[5];
    const float* norm_w     = (const float*)d_in[6];
    const float* W_out      = (const float*)d_in[7];
    const float* conv_state = (const float*)d_in[8];
    const float* rec_state  = (const float*)d_in[9];
    float* out = (float*)d_out;

    float *qkvz, *y, *beta, *alpha, *attb;
    __half *xh, *wqt, *wot, *goh;
    cudaGetSymbolAddress((void**)&qkvz, g_qkvz);
    cudaGetSymbolAddress((void**)&y,    g_y);
    cudaGetSymbolAddress((void**)&beta, g_beta);
    cudaGetSymbolAddress((void**)&alpha,g_alpha);
    cudaGetSymbolAddress((void**)&attb, g_att);
    cudaGetSymbolAddress((void**)&xh,  g_xh);
    cudaGetSymbolAddress((void**)&wqt, g_wqt);
    cudaGetSymbolAddress((void**)&wot, g_wot);
    cudaGetSymbolAddress((void**)&goh, g_goh);

    cudaFuncSetAttribute(h16gemm, cudaFuncAttributeMaxDynamicSharedMemorySize,
                         GEMM_SMEM);

    // 0) operand prep
    to_half<<<(BT * CC / 8 + 255) / 256, 256>>>(x, xh, BT * CC / 8);
    transpose_half<<<dim3(QKVZ_N / 32, CC / 32), 256>>>(W_qkvz, wqt, CC, QKVZ_N);
    transpose_half<<<dim3(CC / 32, CC / 32), 256>>>(W_out, wot, CC, CC);

    // 1) qkvz = x @ W_qkvz  (fp16 mma.m16n8k16)
    h16gemm<<<dim3(QKVZ_N / 256, BT / 128), 256, GEMM_SMEM>>>(
        xh, wqt, qkvz, BT, QKVZ_N, CC);
    // 2) beta/alpha
    ba_kernel<<<BT, 128>>>(x, W_b, W_a, beta, alpha);
    // 3) conv + silu + l2norm
    conv_kernel<<<BT, 256>>>(qkvz, conv_w, conv_state, input_pos, y);
    // 4) recurrence (cp.async pipelined)
    recur_kernel<<<dim3(4, 32), 256>>>(y, beta, alpha, rec_state, input_pos, attb);
    // 5) rmsnorm + gate -> fp16
    gate_kernel<<<BT, 256>>>(attb, qkvz, norm_w, goh);
    // 6) out = gated @ W_out  (fp16 mma.m16n8k16)
    h16gemm<<<dim3(CC / 256, BT / 128), 256, GEMM_SMEM>>>(
        goh, wot, out, BT, CC, CC);
}